// round 15
// baseline (speedup 1.0000x reference)
#include <cuda_runtime.h>
#include <cuda_fp16.h>
#include <cstdint>

#define L_DIM 1024
#define H_DIM 512
#define C_DIM 8
#define BC_DIM 16

// GEMM tiling: CTA 128x128, 4 warps (2x2), warp tile 64x64
#define BM 128
#define BN 128
#define STAGES 3
#define KSTEPS 8
#define NKK 32
#define A_STG_BYTES 16384
#define STG_BYTES   32768
#define SMEM_DYN (STAGES * STG_BYTES)   // 96 KB

#define PSH 520    // pack stage row stride in halves

// ---- static device scratch ----
__device__ float g_av[BC_DIM * L_DIM];
__device__ float g_bv[BC_DIM * L_DIM];
__device__ uint4 g_pa[(size_t)BC_DIM * 64 * NKK * 32];
__device__ uint4 g_pb[(size_t)BC_DIM * 64 * NKK * 32];
__device__ __half g_dm[(size_t)BC_DIM * L_DIM * L_DIM];

// ---------------- helpers ----------------
__device__ __forceinline__ uint32_t h2pack(float a, float b) {
    __half2 h = __floats2half2_rn(a, b);
    return *(uint32_t*)&h;
}
__device__ __forceinline__ uint32_t hmul2u(uint32_t a, uint32_t b) {
    __half2 r = __hmul2(*(__half2*)&a, *(__half2*)&b);
    return *(uint32_t*)&r;
}
__device__ __forceinline__ float2 h2f2(uint32_t x) {
    return __half22float2(*(__half2*)&x);
}
#define CP_ASYNC16(saddr, gaddr) \
    asm volatile("cp.async.cg.shared.global [%0], [%1], 16;" :: "r"(saddr), "l"(gaddr) : "memory")
#define CP_COMMIT() asm volatile("cp.async.commit_group;" ::: "memory")
#define CP_WAIT1()  asm volatile("cp.async.wait_group 1;" ::: "memory")

__device__ __forceinline__ uint32_t smem_u32(const void* p) {
    uint32_t a;
    asm("{ .reg .u64 t; cvta.to.shared.u64 t, %1; cvt.u32.u64 %0, t; }" : "=r"(a) : "l"(p));
    return a;
}
__device__ __forceinline__ void mma_f16(float* d, const uint32_t* a, uint32_t b0, uint32_t b1) {
    asm volatile(
        "mma.sync.aligned.m16n8k16.row.col.f32.f16.f16.f32 "
        "{%0,%1,%2,%3}, {%4,%5,%6,%7}, {%8,%9}, {%0,%1,%2,%3};"
        : "+f"(d[0]), "+f"(d[1]), "+f"(d[2]), "+f"(d[3])
        : "r"(a[0]), "r"(a[1]), "r"(a[2]), "r"(a[3]), "r"(b0), "r"(b1));
}

// ---------------------------------------------------------------------------
// Kernel 1: pack v3 — fp16 staging + smem-cached weight vectors.
// grid (128, 16): x<64 -> A tile I=x ; x>=64 -> B pair Jp=x-64.
// ---------------------------------------------------------------------------
__global__ void pack_kernel(const float* __restrict__ start,
                            const float* __restrict__ endp,
                            const float* __restrict__ v) {
    __shared__ __half stage[16 * PSH];
    __shared__ float w_s[512];
    __shared__ uint32_t vh_s[256];
    __shared__ float dots[16];
    const int bc = blockIdx.y;
    const int tid = threadIdx.x;
    const int w = tid >> 5, lane = tid & 31;
    const int g = lane >> 2, t = lane & 3;

    const bool isA = (blockIdx.x < 64);
    const int T = isA ? blockIdx.x : blockIdx.x - 64;
    const float* src = (isA ? start : endp) +
                       (size_t)bc * L_DIM * H_DIM + (size_t)(T * 16) * H_DIM;

    // weights into smem (bit-identical arithmetic to the global-load version)
    {
        int c = tid;
        if (isA) {
            w_s[c]       = v[c]       + v[1024 + c];
            w_s[c + 256] = v[c + 256] + v[1280 + c];
            vh_s[c] = h2pack(v[1536 + 2 * c], v[1537 + 2 * c]);
        } else {
            w_s[c]       = v[512 + c] - v[1024 + c];
            w_s[c + 256] = v[768 + c] - v[1280 + c];
        }
    }

    // pass 1: stage 16 rows x 512 as fp16, coalesced LDG.128 + STS.64
#pragma unroll
    for (int i = 0; i < 8; i++) {
        int idx = tid + 256 * i;
        int r = idx >> 7, c4 = idx & 127;
        float4 x = *(const float4*)(src + (size_t)r * H_DIM + c4 * 4);
        uint2 st;
        st.x = h2pack(x.x, x.y);
        st.y = h2pack(x.z, x.w);
        *(uint2*)&stage[r * PSH + c4 * 4] = st;
    }
    if (tid < 16) dots[tid] = 0.f;
    __syncthreads();

    const __half* row0 = &stage[g * PSH];
    const __half* row1 = &stage[(g + 8) * PSH];
    uint4* outp = (isA ? g_pa : g_pb) + ((size_t)(bc * 64 + T) * NKK) * 32 + lane;

    float d0 = 0.f, d1 = 0.f;
#pragma unroll
    for (int it = 0; it < 4; it++) {
        int KK = w * 4 + it;
        int c0 = KK * 16 + t * 2;
        uint32_t x00 = *(const uint32_t*)&row0[c0];
        uint32_t x01 = *(const uint32_t*)&row0[c0 + 8];
        uint32_t x10 = *(const uint32_t*)&row1[c0];
        uint32_t x11 = *(const uint32_t*)&row1[c0 + 8];
        float2 f00 = h2f2(x00), f01 = h2f2(x01), f10 = h2f2(x10), f11 = h2f2(x11);
        float2 w0 = *(const float2*)&w_s[c0];
        float2 w1 = *(const float2*)&w_s[c0 + 8];
        d0 += f00.x * w0.x + f00.y * w0.y + f01.x * w1.x + f01.y * w1.y;
        d1 += f10.x * w0.x + f10.y * w0.y + f11.x * w1.x + f11.y * w1.y;
        uint4 o;
        if (isA) {
            uint32_t vh0 = vh_s[c0 >> 1];
            uint32_t vh1 = vh_s[(c0 + 8) >> 1];
            o.x = hmul2u(x00, vh0);
            o.y = hmul2u(x10, vh0);
            o.z = hmul2u(x01, vh1);
            o.w = hmul2u(x11, vh1);
        } else {
            o.x = x00;
            o.y = x01;
            o.z = x10;
            o.w = x11;
        }
        outp[(size_t)KK * 32] = o;
    }
    d0 += __shfl_xor_sync(0xFFFFFFFFu, d0, 1);
    d0 += __shfl_xor_sync(0xFFFFFFFFu, d0, 2);
    d1 += __shfl_xor_sync(0xFFFFFFFFu, d1, 1);
    d1 += __shfl_xor_sync(0xFFFFFFFFu, d1, 2);
    if (t == 0) { atomicAdd(&dots[g], d0); atomicAdd(&dots[g + 8], d1); }
    __syncthreads();
    if (tid < 16) {
        float* dst = isA ? g_av : g_bv;
        dst[bc * L_DIM + T * 16 + tid] = dots[tid];
    }
}

// ---------------------------------------------------------------------------
// Kernel 2: FP16 mma.sync GEMM (exact R11/R14 kernel).
// grid (8, 8, 16), 128 threads, 2 CTA/SM.
// ---------------------------------------------------------------------------
__global__ __launch_bounds__(128, 2)
void gemm_mma(__half* __restrict__ dm) {
    extern __shared__ __align__(16) char smem[];
    __shared__ float av_s[BM], bv_s[BN];

    const int tid = threadIdx.x;
    const int bc = blockIdx.z;
    const int mtile = blockIdx.x * BN;
    const int ltile = blockIdx.y * BM;
    const int Ib = blockIdx.y * 8;
    const int Jbp = blockIdx.x * 8;

    const uint32_t smem_b = smem_u32(smem);

    const char* paB = (const char*)(g_pa +
        (((size_t)(bc * 64 + Ib + (tid >> 7)) * NKK + ((tid >> 5) & 3)) * 32 + (tid & 31)));
    const char* pbB = (const char*)(g_pb +
        (((size_t)(bc * 64 + Jbp + (tid >> 7)) * NKK + ((tid >> 5) & 3)) * 32 + (tid & 31)));
    const uint32_t sA = smem_b + tid * 16;
    const uint32_t sB = smem_b + A_STG_BYTES + tid * 16;

#define FILL(S, BUF) do {                                                      \
        const size_t _gadv = (size_t)(S) * 2048;                               \
        const uint32_t _o = (BUF) * STG_BYTES;                                 \
        _Pragma("unroll")                                                      \
        for (int _i = 0; _i < 8; _i++) {                                       \
            CP_ASYNC16(sA + _o + _i * 2048, paB + _gadv + (size_t)_i * 16384); \
            CP_ASYNC16(sB + _o + _i * 2048, pbB + _gadv + (size_t)_i * 16384); \
        } } while (0)

    FILL(0, 0); CP_COMMIT();
    FILL(1, 1); CP_COMMIT();

    av_s[tid] = g_av[bc * L_DIM + ltile + tid];
    bv_s[tid] = g_bv[bc * L_DIM + mtile + tid];

    const int wid = tid >> 5, lane = tid & 31;
    const int warp_m = wid >> 1, warp_n = wid & 1;
    const int g = lane >> 2, t = lane & 3;

    float d[4][8][4];
#pragma unroll
    for (int i = 0; i < 4; i++)
#pragma unroll
        for (int j = 0; j < 8; j++)
#pragma unroll
            for (int q = 0; q < 4; q++) d[i][j][q] = 0.f;

    for (int s = 0; s < KSTEPS; s++) {
        const int buf = s % STAGES;
        CP_WAIT1();
        __syncthreads();
        if (s + 2 < KSTEPS) FILL(s + 2, (s + 2) % STAGES);
        CP_COMMIT();

        const uint4* Ab = (const uint4*)(smem + buf * STG_BYTES);
        const uint4* Bb = (const uint4*)(smem + buf * STG_BYTES + A_STG_BYTES);

#pragma unroll
        for (int kk = 0; kk < 4; kk++) {
            uint32_t afr[4][4];
            uint4 bq[4];
#pragma unroll
            for (int i = 0; i < 4; i++) {
                const uint4 va = Ab[((warp_m * 4 + i) * 4 + kk) * 32 + lane];
                afr[i][0] = va.x; afr[i][1] = va.y; afr[i][2] = va.z; afr[i][3] = va.w;
            }
#pragma unroll
            for (int p = 0; p < 4; p++)
                bq[p] = Bb[((warp_n * 4 + p) * 4 + kk) * 32 + lane];
#pragma unroll
            for (int i = 0; i < 4; i++)
#pragma unroll
                for (int p = 0; p < 4; p++) {
                    mma_f16(d[i][2 * p],     afr[i], bq[p].x, bq[p].y);
                    mma_f16(d[i][2 * p + 1], afr[i], bq[p].z, bq[p].w);
                }
        }
    }

#pragma unroll
    for (int i = 0; i < 4; i++) {
        const int lr0 = warp_m * 64 + i * 16 + g;
        const float av0 = av_s[lr0], av1 = av_s[lr0 + 8];
        __half* row0 = dm + ((size_t)bc * L_DIM + ltile + lr0) * L_DIM + mtile;
        __half* row1 = row0 + (size_t)8 * L_DIM;
#pragma unroll
        for (int j = 0; j < 8; j++) {
            const int lc = warp_n * 64 + j * 8 + t * 2;
            const float bv0 = bv_s[lc], bv1 = bv_s[lc + 1];
            *(__half2*)(row0 + lc) = __floats2half2_rn(d[i][j][0] + av0 + bv0,
                                                       d[i][j][1] + av0 + bv1);
            *(__half2*)(row1 + lc) = __floats2half2_rn(d[i][j][2] + av1 + bv0,
                                                       d[i][j][3] + av1 + bv1);
        }
    }
}

// ---------------------------------------------------------------------------
// Kernel 3: transpose  out[b,l,m,c] = float(g_dm[b*8+c][l][m]); 4 m per thread.
// ---------------------------------------------------------------------------
__global__ void transpose_kernel(const __half* __restrict__ dm, float* __restrict__ out) {
    size_t e = (size_t)blockIdx.x * blockDim.x + threadIdx.x;   // over b*l*(m/4)
    int m4 = (int)(e & 255) * 4;
    int l  = (int)((e >> 8) & 1023);
    int b  = (int)(e >> 18);
    const __half* base = dm + (size_t)b * 8388608 + (size_t)l * 1024 + m4;
    float2 f0[8], f1[8];
#pragma unroll
    for (int c = 0; c < 8; c++) {
        uint2 u = *(const uint2*)(base + (size_t)c * 1048576);
        f0[c] = h2f2(u.x);     // m4+0, m4+1
        f1[c] = h2f2(u.y);     // m4+2, m4+3
    }
    float4* op = (float4*)(out + e * 32);
    float4 o;
    o.x = f0[0].x; o.y = f0[1].x; o.z = f0[2].x; o.w = f0[3].x; op[0] = o;
    o.x = f0[4].x; o.y = f0[5].x; o.z = f0[6].x; o.w = f0[7].x; op[1] = o;
    o.x = f0[0].y; o.y = f0[1].y; o.z = f0[2].y; o.w = f0[3].y; op[2] = o;
    o.x = f0[4].y; o.y = f0[5].y; o.z = f0[6].y; o.w = f0[7].y; op[3] = o;
    o.x = f1[0].x; o.y = f1[1].x; o.z = f1[2].x; o.w = f1[3].x; op[4] = o;
    o.x = f1[4].x; o.y = f1[5].x; o.z = f1[6].x; o.w = f1[7].x; op[5] = o;
    o.x = f1[0].y; o.y = f1[1].y; o.z = f1[2].y; o.w = f1[3].y; op[6] = o;
    o.x = f1[4].y; o.y = f1[5].y; o.z = f1[6].y; o.w = f1[7].y; op[7] = o;
}

extern "C" void kernel_launch(void* const* d_in, const int* in_sizes, int n_in,
                              void* d_out, int out_size) {
    const float* start = (const float*)d_in[0];
    const float* endp  = (const float*)d_in[1];
    const float* v     = (const float*)d_in[2];
    float* out = (float*)d_out;

    static bool attr_set = false;
    if (!attr_set) {
        cudaFuncSetAttribute(gemm_mma, cudaFuncAttributeMaxDynamicSharedMemorySize, SMEM_DYN);
        attr_set = true;
    }

    __half* dm;
    cudaGetSymbolAddress((void**)&dm, g_dm);

    pack_kernel<<<dim3(128, BC_DIM), 256>>>(start, endp, v);
    gemm_mma<<<dim3(8, 8, BC_DIM), 128, SMEM_DYN>>>(dm);
    transpose_kernel<<<2048, 256>>>(dm, out);
}

// round 16
// speedup vs baseline: 1.1519x; 1.1519x over previous
#include <cuda_runtime.h>
#include <cuda_fp16.h>
#include <cstdint>

#define L_DIM 1024
#define H_DIM 512
#define C_DIM 8
#define BC_DIM 16

// GEMM tiling: CTA 128x128, 4 warps (2x2), warp tile 64x64
#define BM 128
#define BN 128
#define STAGES 3
#define KSTEPS 8
#define NKK 32
#define A_STG_BYTES 16384
#define STG_BYTES   32768
#define SMEM_DYN (STAGES * STG_BYTES)   // 96 KB

#define PSH 520    // pack stage row stride in halves

// ---- static device scratch ----
__device__ float g_av[BC_DIM * L_DIM];
__device__ float g_bv[BC_DIM * L_DIM];
__device__ uint4 g_pa[(size_t)BC_DIM * 64 * NKK * 32];
__device__ uint4 g_pb[(size_t)BC_DIM * 64 * NKK * 32];
__device__ __half g_dm[(size_t)BC_DIM * L_DIM * L_DIM];

// ---------------- helpers ----------------
__device__ __forceinline__ uint32_t h2pack(float a, float b) {
    __half2 h = __floats2half2_rn(a, b);
    return *(uint32_t*)&h;
}
__device__ __forceinline__ uint32_t hmul2u(uint32_t a, uint32_t b) {
    __half2 r = __hmul2(*(__half2*)&a, *(__half2*)&b);
    return *(uint32_t*)&r;
}
__device__ __forceinline__ float2 h2f2(uint32_t x) {
    return __half22float2(*(__half2*)&x);
}
#define CP_ASYNC16(saddr, gaddr) \
    asm volatile("cp.async.cg.shared.global [%0], [%1], 16;" :: "r"(saddr), "l"(gaddr) : "memory")
#define CP_COMMIT() asm volatile("cp.async.commit_group;" ::: "memory")
#define CP_WAIT1()  asm volatile("cp.async.wait_group 1;" ::: "memory")

__device__ __forceinline__ uint32_t smem_u32(const void* p) {
    uint32_t a;
    asm("{ .reg .u64 t; cvta.to.shared.u64 t, %1; cvt.u32.u64 %0, t; }" : "=r"(a) : "l"(p));
    return a;
}
__device__ __forceinline__ void mma_f16(float* d, const uint32_t* a, uint32_t b0, uint32_t b1) {
    asm volatile(
        "mma.sync.aligned.m16n8k16.row.col.f32.f16.f16.f32 "
        "{%0,%1,%2,%3}, {%4,%5,%6,%7}, {%8,%9}, {%0,%1,%2,%3};"
        : "+f"(d[0]), "+f"(d[1]), "+f"(d[2]), "+f"(d[3])
        : "r"(a[0]), "r"(a[1]), "r"(a[2]), "r"(a[3]), "r"(b0), "r"(b1));
}

// ---------------------------------------------------------------------------
// Kernel 1: pack v3 — fp16 staging + smem-cached weight vectors (R15, kept).
// grid (128, 16): x<64 -> A tile I=x ; x>=64 -> B pair Jp=x-64.
// ---------------------------------------------------------------------------
__global__ void pack_kernel(const float* __restrict__ start,
                            const float* __restrict__ endp,
                            const float* __restrict__ v) {
    __shared__ __half stage[16 * PSH];
    __shared__ float w_s[512];
    __shared__ uint32_t vh_s[256];
    __shared__ float dots[16];
    const int bc = blockIdx.y;
    const int tid = threadIdx.x;
    const int w = tid >> 5, lane = tid & 31;
    const int g = lane >> 2, t = lane & 3;

    const bool isA = (blockIdx.x < 64);
    const int T = isA ? blockIdx.x : blockIdx.x - 64;
    const float* src = (isA ? start : endp) +
                       (size_t)bc * L_DIM * H_DIM + (size_t)(T * 16) * H_DIM;

    {
        int c = tid;
        if (isA) {
            w_s[c]       = v[c]       + v[1024 + c];
            w_s[c + 256] = v[c + 256] + v[1280 + c];
            vh_s[c] = h2pack(v[1536 + 2 * c], v[1537 + 2 * c]);
        } else {
            w_s[c]       = v[512 + c] - v[1024 + c];
            w_s[c + 256] = v[768 + c] - v[1280 + c];
        }
    }

#pragma unroll
    for (int i = 0; i < 8; i++) {
        int idx = tid + 256 * i;
        int r = idx >> 7, c4 = idx & 127;
        float4 x = *(const float4*)(src + (size_t)r * H_DIM + c4 * 4);
        uint2 st;
        st.x = h2pack(x.x, x.y);
        st.y = h2pack(x.z, x.w);
        *(uint2*)&stage[r * PSH + c4 * 4] = st;
    }
    if (tid < 16) dots[tid] = 0.f;
    __syncthreads();

    const __half* row0 = &stage[g * PSH];
    const __half* row1 = &stage[(g + 8) * PSH];
    uint4* outp = (isA ? g_pa : g_pb) + ((size_t)(bc * 64 + T) * NKK) * 32 + lane;

    float d0 = 0.f, d1 = 0.f;
#pragma unroll
    for (int it = 0; it < 4; it++) {
        int KK = w * 4 + it;
        int c0 = KK * 16 + t * 2;
        uint32_t x00 = *(const uint32_t*)&row0[c0];
        uint32_t x01 = *(const uint32_t*)&row0[c0 + 8];
        uint32_t x10 = *(const uint32_t*)&row1[c0];
        uint32_t x11 = *(const uint32_t*)&row1[c0 + 8];
        float2 f00 = h2f2(x00), f01 = h2f2(x01), f10 = h2f2(x10), f11 = h2f2(x11);
        float2 w0 = *(const float2*)&w_s[c0];
        float2 w1 = *(const float2*)&w_s[c0 + 8];
        d0 += f00.x * w0.x + f00.y * w0.y + f01.x * w1.x + f01.y * w1.y;
        d1 += f10.x * w0.x + f10.y * w0.y + f11.x * w1.x + f11.y * w1.y;
        uint4 o;
        if (isA) {
            uint32_t vh0 = vh_s[c0 >> 1];
            uint32_t vh1 = vh_s[(c0 + 8) >> 1];
            o.x = hmul2u(x00, vh0);
            o.y = hmul2u(x10, vh0);
            o.z = hmul2u(x01, vh1);
            o.w = hmul2u(x11, vh1);
        } else {
            o.x = x00;
            o.y = x01;
            o.z = x10;
            o.w = x11;
        }
        outp[(size_t)KK * 32] = o;
    }
    d0 += __shfl_xor_sync(0xFFFFFFFFu, d0, 1);
    d0 += __shfl_xor_sync(0xFFFFFFFFu, d0, 2);
    d1 += __shfl_xor_sync(0xFFFFFFFFu, d1, 1);
    d1 += __shfl_xor_sync(0xFFFFFFFFu, d1, 2);
    if (t == 0) { atomicAdd(&dots[g], d0); atomicAdd(&dots[g + 8], d1); }
    __syncthreads();
    if (tid < 16) {
        float* dst = isA ? g_av : g_bv;
        dst[bc * L_DIM + T * 16 + tid] = dots[tid];
    }
}

// ---------------------------------------------------------------------------
// Kernel 2: FP16 mma.sync GEMM (exact R11/R14 kernel).
// grid (8, 8, 16), 128 threads, 2 CTA/SM.
// ---------------------------------------------------------------------------
__global__ __launch_bounds__(128, 2)
void gemm_mma(__half* __restrict__ dm) {
    extern __shared__ __align__(16) char smem[];
    __shared__ float av_s[BM], bv_s[BN];

    const int tid = threadIdx.x;
    const int bc = blockIdx.z;
    const int mtile = blockIdx.x * BN;
    const int ltile = blockIdx.y * BM;
    const int Ib = blockIdx.y * 8;
    const int Jbp = blockIdx.x * 8;

    const uint32_t smem_b = smem_u32(smem);

    const char* paB = (const char*)(g_pa +
        (((size_t)(bc * 64 + Ib + (tid >> 7)) * NKK + ((tid >> 5) & 3)) * 32 + (tid & 31)));
    const char* pbB = (const char*)(g_pb +
        (((size_t)(bc * 64 + Jbp + (tid >> 7)) * NKK + ((tid >> 5) & 3)) * 32 + (tid & 31)));
    const uint32_t sA = smem_b + tid * 16;
    const uint32_t sB = smem_b + A_STG_BYTES + tid * 16;

#define FILL(S, BUF) do {                                                      \
        const size_t _gadv = (size_t)(S) * 2048;                               \
        const uint32_t _o = (BUF) * STG_BYTES;                                 \
        _Pragma("unroll")                                                      \
        for (int _i = 0; _i < 8; _i++) {                                       \
            CP_ASYNC16(sA + _o + _i * 2048, paB + _gadv + (size_t)_i * 16384); \
            CP_ASYNC16(sB + _o + _i * 2048, pbB + _gadv + (size_t)_i * 16384); \
        } } while (0)

    FILL(0, 0); CP_COMMIT();
    FILL(1, 1); CP_COMMIT();

    av_s[tid] = g_av[bc * L_DIM + ltile + tid];
    bv_s[tid] = g_bv[bc * L_DIM + mtile + tid];

    const int wid = tid >> 5, lane = tid & 31;
    const int warp_m = wid >> 1, warp_n = wid & 1;
    const int g = lane >> 2, t = lane & 3;

    float d[4][8][4];
#pragma unroll
    for (int i = 0; i < 4; i++)
#pragma unroll
        for (int j = 0; j < 8; j++)
#pragma unroll
            for (int q = 0; q < 4; q++) d[i][j][q] = 0.f;

    for (int s = 0; s < KSTEPS; s++) {
        const int buf = s % STAGES;
        CP_WAIT1();
        __syncthreads();
        if (s + 2 < KSTEPS) FILL(s + 2, (s + 2) % STAGES);
        CP_COMMIT();

        const uint4* Ab = (const uint4*)(smem + buf * STG_BYTES);
        const uint4* Bb = (const uint4*)(smem + buf * STG_BYTES + A_STG_BYTES);

#pragma unroll
        for (int kk = 0; kk < 4; kk++) {
            uint32_t afr[4][4];
            uint4 bq[4];
#pragma unroll
            for (int i = 0; i < 4; i++) {
                const uint4 va = Ab[((warp_m * 4 + i) * 4 + kk) * 32 + lane];
                afr[i][0] = va.x; afr[i][1] = va.y; afr[i][2] = va.z; afr[i][3] = va.w;
            }
#pragma unroll
            for (int p = 0; p < 4; p++)
                bq[p] = Bb[((warp_n * 4 + p) * 4 + kk) * 32 + lane];
#pragma unroll
            for (int i = 0; i < 4; i++)
#pragma unroll
                for (int p = 0; p < 4; p++) {
                    mma_f16(d[i][2 * p],     afr[i], bq[p].x, bq[p].y);
                    mma_f16(d[i][2 * p + 1], afr[i], bq[p].z, bq[p].w);
                }
        }
    }

#pragma unroll
    for (int i = 0; i < 4; i++) {
        const int lr0 = warp_m * 64 + i * 16 + g;
        const float av0 = av_s[lr0], av1 = av_s[lr0 + 8];
        __half* row0 = dm + ((size_t)bc * L_DIM + ltile + lr0) * L_DIM + mtile;
        __half* row1 = row0 + (size_t)8 * L_DIM;
#pragma unroll
        for (int j = 0; j < 8; j++) {
            const int lc = warp_n * 64 + j * 8 + t * 2;
            const float bv0 = bv_s[lc], bv1 = bv_s[lc + 1];
            *(__half2*)(row0 + lc) = __floats2half2_rn(d[i][j][0] + av0 + bv0,
                                                       d[i][j][1] + av0 + bv1);
            *(__half2*)(row1 + lc) = __floats2half2_rn(d[i][j][2] + av1 + bv0,
                                                       d[i][j][3] + av1 + bv1);
        }
    }
}

// ---------------------------------------------------------------------------
// Kernel 3: transpose (R14 version, 2 m per thread — measured good).
// out[b,l,m,c] = float(g_dm[b*8+c][l][m])
// ---------------------------------------------------------------------------
__global__ void transpose_kernel(const __half* __restrict__ dm, float* __restrict__ out) {
    size_t e = (size_t)blockIdx.x * blockDim.x + threadIdx.x;
    int m2 = (int)(e & 511) * 2;
    int l  = (int)((e >> 9) & 1023);
    int b  = (int)(e >> 19);
    const __half* base = dm + (size_t)b * 8388608 + (size_t)l * 1024 + m2;
    float2 f[8];
#pragma unroll
    for (int c = 0; c < 8; c++)
        f[c] = __half22float2(*(const __half2*)(base + (size_t)c * 1048576));
    float4* op = (float4*)(out + e * 16);
    float4 o;
    o.x = f[0].x; o.y = f[1].x; o.z = f[2].x; o.w = f[3].x; op[0] = o;
    o.x = f[4].x; o.y = f[5].x; o.z = f[6].x; o.w = f[7].x; op[1] = o;
    o.x = f[0].y; o.y = f[1].y; o.z = f[2].y; o.w = f[3].y; op[2] = o;
    o.x = f[4].y; o.y = f[5].y; o.z = f[6].y; o.w = f[7].y; op[3] = o;
}

extern "C" void kernel_launch(void* const* d_in, const int* in_sizes, int n_in,
                              void* d_out, int out_size) {
    const float* start = (const float*)d_in[0];
    const float* endp  = (const float*)d_in[1];
    const float* v     = (const float*)d_in[2];
    float* out = (float*)d_out;

    static bool attr_set = false;
    if (!attr_set) {
        cudaFuncSetAttribute(gemm_mma, cudaFuncAttributeMaxDynamicSharedMemorySize, SMEM_DYN);
        attr_set = true;
    }

    __half* dm;
    cudaGetSymbolAddress((void**)&dm, g_dm);

    pack_kernel<<<dim3(128, BC_DIM), 256>>>(start, endp, v);
    gemm_mma<<<dim3(8, 8, BC_DIM), 128, SMEM_DYN>>>(dm);
    transpose_kernel<<<(1u << 20) / 256, 256>>>(dm, out);
}